// round 4
// baseline (speedup 1.0000x reference)
#include <cuda_runtime.h>
#include <math.h>

// Problem dims
#define BB 128
#define SS 1024
#define QMAX 5001          // q ids 0..5000
#define MSLOT 64
#define KDIM 128
#define VDIM 256
#define FDIM 128
#define NT 131072          // BB*SS

typedef unsigned long long ull;

// ---------------- scratch (static device arrays: no allocation) -------------
__device__ float g_Wtab[QMAX * MSLOT];          // softmax(qe @ K^T) per q
__device__ float g_bvE[512];                    // b_value @ [W_erase|W_add]
__device__ float g_PP[10016 * 512];             // W_value @ [W_erase|W_add]
__device__ float g_EAtab[QMAX * 4 * 512];       // [q][r][ erase(256) | add(256) ]
__device__ float g_QStab[QMAX * FDIM];          // qe @ W_summary[256:384] + b_summary
__device__ float g_betatab[QMAX * 3];           // qe @ W_beta + b_beta
__device__ float g_qdtab[QMAX];                 // qe @ W_disc[128:256]
__device__ float g_read[(size_t)NT * VDIM];     // per-step memory reads
__device__ float g_summary[(size_t)NT * FDIM];  // tanh summary

// ---------------- packed f32x2 helpers --------------------------------------
__device__ __forceinline__ ull pack2(float lo, float hi) {
    ull d; asm("mov.b64 %0, {%1, %2};" : "=l"(d) : "f"(lo), "f"(hi)); return d;
}
__device__ __forceinline__ void unpack2(ull v, float& lo, float& hi) {
    asm("mov.b64 {%0, %1}, %2;" : "=f"(lo), "=f"(hi) : "l"(v));
}
__device__ __forceinline__ ull fma2(ull a, ull b, ull c) {
    ull d; asm("fma.rn.f32x2 %0, %1, %2, %3;" : "=l"(d) : "l"(a), "l"(b), "l"(c));
    return d;
}

__device__ __forceinline__ float sigmoidf_(float x) { return 1.0f / (1.0f + expf(-x)); }
__device__ __forceinline__ float softplusf_(float x) {
    return fmaxf(x, 0.0f) + log1pf(expf(-fabsf(x)));
}

// ---------------- L1: fused wtab (softmax table) + bv ------------------------
__global__ void __launch_bounds__(64) wtab_bv_kernel(const float* __restrict__ qe_table,
                                                     const float* __restrict__ key_memory,
                                                     const float* __restrict__ b_value,
                                                     const float* __restrict__ W_erase,
                                                     const float* __restrict__ W_add) {
    if (blockIdx.x == QMAX) {  // bv role: b_value @ [W_erase|W_add]
        int t = threadIdx.x;
        for (int j = t; j < 512; j += 64) {
            const float* W = (j < 256) ? (W_erase + j) : (W_add + (j - 256));
            float a = 0.0f;
            for (int k = 0; k < 256; k++) a = fmaf(b_value[k], W[k * 256], a);
            g_bvE[j] = a;
        }
        return;
    }
    int q = blockIdx.x;
    int m = threadIdx.x;
    __shared__ float qe[KDIM];
    __shared__ float sh_d[MSLOT];
    __shared__ float sh_e[MSLOT];
    qe[m]      = qe_table[q * KDIM + m];
    qe[m + 64] = qe_table[q * KDIM + 64 + m];
    __syncthreads();
    float d = 0.0f;
    #pragma unroll 8
    for (int k = 0; k < KDIM; k++) d = fmaf(qe[k], key_memory[m * KDIM + k], d);
    sh_d[m] = d;
    __syncthreads();
    float mx = -1e30f;
    #pragma unroll 8
    for (int i = 0; i < MSLOT; i++) mx = fmaxf(mx, sh_d[i]);
    float e = expf(d - mx);
    sh_e[m] = e;
    __syncthreads();
    float sum = 0.0f;
    #pragma unroll 8
    for (int i = 0; i < MSLOT; i++) sum += sh_e[i];
    g_Wtab[q * MSLOT + m] = e / sum;
}

// ---------------- L2: SGEMM  PP = W_value(10000x256) @ [W_erase|W_add](256x512)
__global__ void __launch_bounds__(256) sgemm_pp_kernel(const float* __restrict__ A,
                                                       const float* __restrict__ We,
                                                       const float* __restrict__ Wa,
                                                       int M) {
    const int K = 256, N = 512;
    __shared__ float As[8][256];   // duplicated: As[k][2r]=As[k][2r+1]=A[r][k]
    __shared__ float Bs[8][128];
    int tid = threadIdx.x;
    int row0 = blockIdx.y * 128, col0 = blockIdx.x * 128;
    int aRow = tid >> 1, aK4 = (tid & 1) * 4;
    int bK = tid >> 5, bCol = (tid & 31) * 4;
    int tx = tid & 15, ty = tid >> 4;
    ull acc2[8][4];
    #pragma unroll
    for (int i = 0; i < 8; i++)
        #pragma unroll
        for (int j = 0; j < 4; j++) acc2[i][j] = 0ull;

    for (int k0 = 0; k0 < K; k0 += 8) {
        float4 av = make_float4(0, 0, 0, 0);
        int ar = row0 + aRow;
        if (ar < M) av = __ldg((const float4*)(A + (size_t)ar * K + k0 + aK4));
        *(float2*)&As[aK4 + 0][2 * aRow] = make_float2(av.x, av.x);
        *(float2*)&As[aK4 + 1][2 * aRow] = make_float2(av.y, av.y);
        *(float2*)&As[aK4 + 2][2 * aRow] = make_float2(av.z, av.z);
        *(float2*)&As[aK4 + 3][2 * aRow] = make_float2(av.w, av.w);
        int j = col0 + bCol;
        const float* bp = (j < 256) ? (We + (k0 + bK) * 256 + j)
                                    : (Wa + (k0 + bK) * 256 + (j - 256));
        *(float4*)&Bs[bK][bCol] = __ldg((const float4*)bp);
        __syncthreads();
        #pragma unroll
        for (int kk = 0; kk < 8; kk++) {
            ull ra[8], rb[4];
            #pragma unroll
            for (int i = 0; i < 8; i++) ra[i] = *(const ull*)&As[kk][2 * (ty * 8 + i)];
            #pragma unroll
            for (int jp = 0; jp < 4; jp++) rb[jp] = *(const ull*)&Bs[kk][jp * 32 + tx * 2];
            #pragma unroll
            for (int i = 0; i < 8; i++)
                #pragma unroll
                for (int jp = 0; jp < 4; jp++)
                    acc2[i][jp] = fma2(ra[i], rb[jp], acc2[i][jp]);
        }
        __syncthreads();
    }
    #pragma unroll
    for (int i = 0; i < 8; i++) {
        int r = row0 + ty * 8 + i;
        if (r < M) {
            #pragma unroll
            for (int jp = 0; jp < 4; jp++) {
                int c = col0 + jp * 32 + tx * 2;
                float lo, hi; unpack2(acc2[i][jp], lo, hi);
                *(float2*)&g_PP[(size_t)r * N + c] = make_float2(lo, hi);
            }
        }
    }
}

// ---------------- L3: fused ea-table + perq projections ----------------------
#define EA_BLOCKS 40008   // QMAX*4*512/256
__global__ void __launch_bounds__(256) ea_perq_kernel(const float* __restrict__ b_erase,
                                                      const float* __restrict__ b_add,
                                                      const float* __restrict__ qe_table,
                                                      const float* __restrict__ W_summary,
                                                      const float* __restrict__ b_summary,
                                                      const float* __restrict__ W_beta,
                                                      const float* __restrict__ b_beta,
                                                      const float* __restrict__ W_disc) {
    int bid = blockIdx.x;
    int tid = threadIdx.x;
    if (bid < EA_BLOCKS) {  // ea role
        int idx = bid * 256 + tid;
        int v = idx & 511;
        int r = (idx >> 9) & 3;
        int q = idx >> 11;
        float scale = (float)r * (1.0f / 3.0f);
        float p0 = 0.0f, p1 = 0.0f;
        if (q > 0) {
            p0 = __ldg(&g_PP[(size_t)(q - 1) * 512 + v]);
            p1 = __ldg(&g_PP[(size_t)(4999 + q) * 512 + v]);
        }
        float bias = (v < 256) ? b_erase[v] : b_add[v - 256];
        float x = p0 + g_bvE[v] + bias + scale * p1;
        g_EAtab[idx] = (v < 256) ? sigmoidf_(x) : tanhf(x);
        return;
    }
    // perq role
    int q = bid - EA_BLOCKS;
    __shared__ float qe[KDIM];
    if (tid < 128) qe[tid] = qe_table[q * KDIM + tid];
    __syncthreads();
    if (tid < 128) {
        int f = tid;
        float acc = b_summary[f];
        #pragma unroll 8
        for (int d = 0; d < KDIM; d++)
            acc = fmaf(qe[d], W_summary[(256 + d) * FDIM + f], acc);
        g_QStab[q * FDIM + f] = acc;
    } else if (tid < 131) {
        int f = tid - 128;
        float a = b_beta[f];
        for (int d = 0; d < KDIM; d++) a = fmaf(qe[d], W_beta[d * 3 + f], a);
        g_betatab[q * 3 + f] = a;
    } else if (tid == 136) {
        float a = 0.0f;
        for (int d = 0; d < KDIM; d++) a = fmaf(qe[d], W_disc[128 + d], a);
        g_qdtab[q] = a;
    }
}

// ---------------- L4: persistent recurrence scan (3-buffer, distance-2) ------
// 128 CTAs, 512 threads. Thread owns 2 v (v0=2p, v1=2p+1) x 16 m (8 m-pairs),
// p = tid>>2, quarter = tid&3.
__device__ __forceinline__ void scan_pref(int q, int r, int quarter, int p,
                                          ull* W, float2& ee, float2& aa) {
    const ulonglong2* wp = (const ulonglong2*)(g_Wtab + q * MSLOT + quarter * 16);
    ulonglong2 t0 = __ldg(wp), t1 = __ldg(wp + 1), t2 = __ldg(wp + 2), t3 = __ldg(wp + 3);
    W[0] = t0.x; W[1] = t0.y; W[2] = t1.x; W[3] = t1.y;
    W[4] = t2.x; W[5] = t2.y; W[6] = t3.x; W[7] = t3.y;
    const float* ea = g_EAtab + (size_t)(q * 4 + r) * 512;
    ee = __ldg((const float2*)(ea + 2 * p));
    aa = __ldg((const float2*)(ea + 256 + 2 * p));
}

__device__ __forceinline__ void scan_step(ull* R0, ull* R1, const ull* W,
                                          float2 ee, float2 aa,
                                          int quarter, float* outp) {
    ull ne0 = pack2(-ee.x, -ee.x), ne1 = pack2(-ee.y, -ee.y);
    ull a20 = pack2(aa.x, aa.x),   a21 = pack2(aa.y, aa.y);
    ull acc0 = 0ull, acc1 = 0ull;
    #pragma unroll
    for (int i = 0; i < 8; i++) {
        ull t0 = fma2(ne0, R0[i], a20);
        ull t1 = fma2(ne1, R1[i], a21);
        acc0 = fma2(W[i], R0[i], acc0);
        acc1 = fma2(W[i], R1[i], acc1);
        R0[i] = fma2(W[i], t0, R0[i]);
        R1[i] = fma2(W[i], t1, R1[i]);
    }
    float x0, y0, x1, y1;
    unpack2(acc0, x0, y0);
    unpack2(acc1, x1, y1);
    float rd0 = x0 + y0, rd1 = x1 + y1;
    rd0 += __shfl_xor_sync(0xffffffffu, rd0, 1);
    rd0 += __shfl_xor_sync(0xffffffffu, rd0, 2);
    rd1 += __shfl_xor_sync(0xffffffffu, rd1, 1);
    rd1 += __shfl_xor_sync(0xffffffffu, rd1, 2);
    if (quarter == 0) *(float2*)outp = make_float2(rd0, rd1);
}

__global__ void __launch_bounds__(512) scan_kernel(const int* __restrict__ q_data,
                                                   const int* __restrict__ r_data,
                                                   const float* __restrict__ initMv) {
    const int b = blockIdx.x;
    const int tid = threadIdx.x;
    const int quarter = tid & 3;
    const int p = tid >> 2;

    __shared__ int q_sh[SS + 8];
    __shared__ int r_sh[SS + 8];
    for (int i = tid; i < SS; i += 512) {
        q_sh[i] = q_data[b * SS + i];
        r_sh[i] = r_data[b * SS + i];
    }
    if (tid < 8) {  // padding for prefetch over-run (valid table rows)
        q_sh[SS + tid] = q_data[b * SS + SS - 1];
        r_sh[SS + tid] = r_data[b * SS + SS - 1];
    }

    ull R0[8], R1[8];
    #pragma unroll
    for (int i = 0; i < 8; i++) {
        int m = quarter * 16 + 2 * i;
        R0[i] = pack2(initMv[m * VDIM + 2 * p],     initMv[(m + 1) * VDIM + 2 * p]);
        R1[i] = pack2(initMv[m * VDIM + 2 * p + 1], initMv[(m + 1) * VDIM + 2 * p + 1]);
    }
    __syncthreads();

    ull WA[8], WB[8], WC[8];
    float2 eA, aA, eB, aB, eC, aC;
    scan_pref(q_sh[0], r_sh[0], quarter, p, WA, eA, aA);
    scan_pref(q_sh[1], r_sh[1], quarter, p, WB, eB, aB);
    scan_pref(q_sh[2], r_sh[2], quarter, p, WC, eC, aC);

    float* rdbase = g_read + (((size_t)b << 10)) * VDIM + 2 * p;

    // step 0, refill A with step 3  -> from here on, prefetch distance = 2 steps
    scan_step(R0, R1, WA, eA, aA, quarter, rdbase);
    scan_pref(q_sh[3], r_sh[3], quarter, p, WA, eA, aA);

    for (int s = 1; s < SS; s += 3) {
        scan_step(R0, R1, WB, eB, aB, quarter, rdbase + (size_t)s * VDIM);
        scan_pref(q_sh[s + 3], r_sh[s + 3], quarter, p, WB, eB, aB);
        scan_step(R0, R1, WC, eC, aC, quarter, rdbase + (size_t)(s + 1) * VDIM);
        scan_pref(q_sh[s + 4], r_sh[s + 4], quarter, p, WC, eC, aC);
        scan_step(R0, R1, WA, eA, aA, quarter, rdbase + (size_t)(s + 2) * VDIM);
        scan_pref(q_sh[s + 5], r_sh[s + 5], quarter, p, WA, eA, aA);
    }
}

// ---------------- L5: summary SGEMM (131072x256 @ 256x128), f32x2, tanh ------
__global__ void __launch_bounds__(256) sgemm_sum_kernel(const int* __restrict__ q_data,
                                                        const float* __restrict__ W_summary) {
    const int K = 256, N = 128;
    __shared__ float As[8][256];   // duplicated
    __shared__ float Bs[8][128];
    __shared__ int qrow_s[128];
    int tid = threadIdx.x;
    int row0 = blockIdx.x * 128;
    if (tid < 128) qrow_s[tid] = q_data[row0 + tid];
    int aRow = tid >> 1, aK4 = (tid & 1) * 4;
    int bK = tid >> 5, bCol = (tid & 31) * 4;
    int tx = tid & 15, ty = tid >> 4;
    ull acc2[8][4];
    #pragma unroll
    for (int i = 0; i < 8; i++)
        #pragma unroll
        for (int j = 0; j < 4; j++) acc2[i][j] = 0ull;

    const float* A = g_read;
    for (int k0 = 0; k0 < K; k0 += 8) {
        float4 av = __ldg((const float4*)(A + (size_t)(row0 + aRow) * K + k0 + aK4));
        *(float2*)&As[aK4 + 0][2 * aRow] = make_float2(av.x, av.x);
        *(float2*)&As[aK4 + 1][2 * aRow] = make_float2(av.y, av.y);
        *(float2*)&As[aK4 + 2][2 * aRow] = make_float2(av.z, av.z);
        *(float2*)&As[aK4 + 3][2 * aRow] = make_float2(av.w, av.w);
        *(float4*)&Bs[bK][bCol] = __ldg((const float4*)(W_summary + (k0 + bK) * N + bCol));
        __syncthreads();
        #pragma unroll
        for (int kk = 0; kk < 8; kk++) {
            ull ra[8], rb[4];
            #pragma unroll
            for (int i = 0; i < 8; i++) ra[i] = *(const ull*)&As[kk][2 * (ty * 8 + i)];
            #pragma unroll
            for (int jp = 0; jp < 4; jp++) rb[jp] = *(const ull*)&Bs[kk][jp * 32 + tx * 2];
            #pragma unroll
            for (int i = 0; i < 8; i++)
                #pragma unroll
                for (int jp = 0; jp < 4; jp++)
                    acc2[i][jp] = fma2(ra[i], rb[jp], acc2[i][jp]);
        }
        __syncthreads();
    }
    #pragma unroll
    for (int i = 0; i < 8; i++) {
        int rl = ty * 8 + i;
        int r = row0 + rl;
        int q = qrow_s[rl];
        const float* qs = g_QStab + q * FDIM;
        #pragma unroll
        for (int jp = 0; jp < 4; jp++) {
            int c = jp * 32 + tx * 2;
            float lo, hi; unpack2(acc2[i][jp], lo, hi);
            *(float2*)&g_summary[(size_t)r * N + c] =
                make_float2(tanhf(lo + __ldg(qs + c)), tanhf(hi + __ldg(qs + c + 1)));
        }
    }
}

// ---------------- L6: per-token head (theta/alpha/CORAL), 32 tokens/warp -----
__global__ void __launch_bounds__(256) head_kernel(const int* __restrict__ q_data,
                                                   const float* __restrict__ W_theta,
                                                   const float* __restrict__ b_theta,
                                                   const float* __restrict__ W_disc,
                                                   const float* __restrict__ b_disc,
                                                   const float* __restrict__ W_c1,
                                                   const float* __restrict__ b_c1,
                                                   const float* __restrict__ W_c2,
                                                   const float* __restrict__ b_c2,
                                                   const float* __restrict__ coral_w,
                                                   const float* __restrict__ coral_b,
                                                   float* __restrict__ out) {
    __shared__ float sWc1[5 * 64], sBc1[64], sWc2[64 * 32], sBc2[32], sCw[32];
    __shared__ float sWth[128], sWd[128];
    __shared__ float h1s[8][64];
    int tid = threadIdx.x;
    for (int i = tid; i < 320; i += 256) sWc1[i] = W_c1[i];
    for (int i = tid; i < 2048; i += 256) sWc2[i] = W_c2[i];
    if (tid < 64) sBc1[tid] = b_c1[tid];
    if (tid < 32) { sBc2[tid] = b_c2[tid]; sCw[tid] = coral_w[tid]; }
    if (tid < 128) { sWth[tid] = W_theta[tid]; sWd[tid] = W_disc[tid]; }
    __syncthreads();

    int warp = tid >> 5, lane = tid & 31;
    float bth = b_theta[0], bd = b_disc[0];
    float cb0 = coral_b[0], cb1 = coral_b[1], cb2 = coral_b[2];
    float wth0 = sWth[lane], wth1 = sWth[lane + 32], wth2 = sWth[lane + 64], wth3 = sWth[lane + 96];
    float wd0 = sWd[lane], wd1 = sWd[lane + 32], wd2 = sWd[lane + 64], wd3 = sWd[lane + 96];
    float cw = sCw[lane];

    const int TOK = 32;
    size_t base = ((size_t)blockIdx.x * 8 + warp) * TOK;
    for (int t = 0; t < TOK; t++) {
        size_t n = base + t;
        const float* srow = g_summary + n * FDIM;
        float s0 = __ldg(srow + lane), s1 = __ldg(srow + lane + 32);
        float s2 = __ldg(srow + lane + 64), s3 = __ldg(srow + lane + 96);
        float th = s0 * wth0 + s1 * wth1 + s2 * wth2 + s3 * wth3;
        float dp = s0 * wd0 + s1 * wd1 + s2 * wd2 + s3 * wd3;
        #pragma unroll
        for (int o = 16; o; o >>= 1) {
            th += __shfl_xor_sync(0xffffffffu, th, o);
            dp += __shfl_xor_sync(0xffffffffu, dp, o);
        }
        float theta = (th + bth) * 3.0f;
        int q = q_data[n];
        float alpha = softplusf_(dp + g_qdtab[q] + bd);
        float be0 = g_betatab[q * 3 + 0];
        float be1 = g_betatab[q * 3 + 1];
        float be2 = g_betatab[q * 3 + 2];
        float feat[5] = {theta, alpha, be0, be1, be2};

        float h1a = sBc1[lane], h1b = sBc1[lane + 32];
        #pragma unroll
        for (int i = 0; i < 5; i++) {
            h1a = fmaf(feat[i], sWc1[i * 64 + lane], h1a);
            h1b = fmaf(feat[i], sWc1[i * 64 + lane + 32], h1b);
        }
        h1s[warp][lane] = fmaxf(h1a, 0.0f);
        h1s[warp][lane + 32] = fmaxf(h1b, 0.0f);
        __syncwarp();
        float h2 = sBc2[lane];
        #pragma unroll
        for (int i = 0; i < 64; i++) h2 = fmaf(h1s[warp][i], sWc2[i * 32 + lane], h2);
        h2 = fmaxf(h2, 0.0f);
        float lg = h2 * cw;
        #pragma unroll
        for (int o = 16; o; o >>= 1) lg += __shfl_xor_sync(0xffffffffu, lg, o);

        if (lane == 0) {
            float l0 = lg + cb0, l1 = lg + cb1, l2 = lg + cb2;
            float c1 = sigmoidf_(l0);
            float c2 = c1 * sigmoidf_(l1);
            float c3 = c2 * sigmoidf_(l2);
            const size_t N = NT;
            out[n] = theta;
            out[N + n * 3 + 0] = be0;
            out[N + n * 3 + 1] = be1;
            out[N + n * 3 + 2] = be2;
            out[4 * N + n] = alpha;
            out[5 * N + n * 4 + 0] = 1.0f - c1;
            out[5 * N + n * 4 + 1] = c1 - c2;
            out[5 * N + n * 4 + 2] = c2 - c3;
            out[5 * N + n * 4 + 3] = c3;
            out[9 * N + n * 3 + 0] = l0;
            out[9 * N + n * 3 + 1] = l1;
            out[9 * N + n * 3 + 2] = l2;
        }
        __syncwarp();
    }
}

// ---------------- launch -----------------------------------------------------
extern "C" void kernel_launch(void* const* d_in, const int* in_sizes, int n_in,
                              void* d_out, int out_size) {
    const int*   q_data   = (const int*)d_in[0];
    const int*   r_data   = (const int*)d_in[1];
    const float* qe_table = (const float*)d_in[2];
    const float* key_mem  = (const float*)d_in[3];
    const float* initMv   = (const float*)d_in[4];
    const float* W_value  = (const float*)d_in[5];
    const float* b_value  = (const float*)d_in[6];
    const float* W_erase  = (const float*)d_in[7];
    const float* b_erase  = (const float*)d_in[8];
    const float* W_add    = (const float*)d_in[9];
    const float* b_add    = (const float*)d_in[10];
    const float* W_summary= (const float*)d_in[11];
    const float* b_summary= (const float*)d_in[12];
    const float* W_theta  = (const float*)d_in[13];
    const float* b_theta  = (const float*)d_in[14];
    const float* W_beta   = (const float*)d_in[15];
    const float* b_beta   = (const float*)d_in[16];
    const float* W_disc   = (const float*)d_in[17];
    const float* b_disc   = (const float*)d_in[18];
    const float* W_c1     = (const float*)d_in[19];
    const float* b_c1     = (const float*)d_in[20];
    const float* W_c2     = (const float*)d_in[21];
    const float* b_c2     = (const float*)d_in[22];
    const float* coral_w  = (const float*)d_in[23];
    const float* coral_b  = (const float*)d_in[24];
    float* out = (float*)d_out;

    // L1: wtab + bv
    wtab_bv_kernel<<<QMAX + 1, 64>>>(qe_table, key_mem, b_value, W_erase, W_add);
    // L2: PP GEMM
    {
        dim3 g(4, 79);
        sgemm_pp_kernel<<<g, 256>>>(W_value, W_erase, W_add, 10000);
    }
    // L3: ea table + perq
    ea_perq_kernel<<<EA_BLOCKS + QMAX, 256>>>(b_erase, b_add, qe_table,
                                              W_summary, b_summary, W_beta, b_beta, W_disc);
    // L4: scan (this is launch #4 -> the one ncu captures)
    scan_kernel<<<BB, 512>>>(q_data, r_data, initMv);
    // L5: summary GEMM
    sgemm_sum_kernel<<<NT / 128, 256>>>(q_data, W_summary);
    // L6: head
    head_kernel<<<NT / (8 * 32), 256>>>(q_data, W_theta, b_theta, W_disc, b_disc,
                                        W_c1, b_c1, W_c2, b_c2, coral_w, coral_b, out);
}

// round 5
// speedup vs baseline: 1.0818x; 1.0818x over previous
#include <cuda_runtime.h>
#include <math.h>

// Problem dims
#define BB 128
#define SS 1024
#define QMAX 5001          // q ids 0..5000
#define MSLOT 64
#define KDIM 128
#define VDIM 256
#define FDIM 128
#define NT 131072          // BB*SS

typedef unsigned long long ull;

// ---------------- scratch (static device arrays: no allocation) -------------
__device__ float g_Wtab[QMAX * MSLOT];          // softmax(qe @ K^T) per q
__device__ float g_bvE2[512];                   // b_value@[We|Wa] + [b_erase|b_add]
__device__ float g_EAtab[QMAX * 4 * 512];       // [q][r][ erase(256) | add(256) ]
__device__ float g_QStab[QMAX * FDIM];          // qe @ W_summary[256:384] + b_summary
__device__ float g_betatab[QMAX * 3];           // qe @ W_beta + b_beta
__device__ float g_qdtab[QMAX];                 // qe @ W_disc[128:256]
__device__ float g_read[(size_t)NT * VDIM];     // per-step memory reads
__device__ float g_summary[(size_t)NT * FDIM];  // tanh summary

// ---------------- packed f32x2 helpers --------------------------------------
__device__ __forceinline__ ull pack2(float lo, float hi) {
    ull d; asm("mov.b64 %0, {%1, %2};" : "=l"(d) : "f"(lo), "f"(hi)); return d;
}
__device__ __forceinline__ void unpack2(ull v, float& lo, float& hi) {
    asm("mov.b64 {%0, %1}, %2;" : "=f"(lo), "=f"(hi) : "l"(v));
}
__device__ __forceinline__ ull fma2(ull a, ull b, ull c) {
    ull d; asm("fma.rn.f32x2 %0, %1, %2, %3;" : "=l"(d) : "l"(a), "l"(b), "l"(c));
    return d;
}

__device__ __forceinline__ float sigmoidf_(float x) { return 1.0f / (1.0f + expf(-x)); }
__device__ __forceinline__ float softplusf_(float x) {
    return fmaxf(x, 0.0f) + log1pf(expf(-fabsf(x)));
}

// ---------------- K1: fused wtab + perq (per q) ; last block: bv + EA row0 ---
__global__ void __launch_bounds__(128) wtab_perq_kernel(const float* __restrict__ qe_table,
                                                        const float* __restrict__ key_memory,
                                                        const float* __restrict__ b_value,
                                                        const float* __restrict__ W_erase,
                                                        const float* __restrict__ W_add,
                                                        const float* __restrict__ b_erase,
                                                        const float* __restrict__ b_add,
                                                        const float* __restrict__ W_summary,
                                                        const float* __restrict__ b_summary,
                                                        const float* __restrict__ W_beta,
                                                        const float* __restrict__ b_beta,
                                                        const float* __restrict__ W_disc) {
    int t = threadIdx.x;
    if (blockIdx.x == QMAX) {   // bv role: bvE2 + EAtab[q=0]
        for (int j = t; j < 512; j += 128) {
            const float* W = (j < 256) ? (W_erase + j) : (W_add + (j - 256));
            float a = 0.0f;
            for (int k = 0; k < 256; k++) a = fmaf(b_value[k], W[k * 256], a);
            float bias = (j < 256) ? b_erase[j] : b_add[j - 256];
            float x = a + bias;
            g_bvE2[j] = x;
            float act = (j < 256) ? sigmoidf_(x) : tanhf(x);
            #pragma unroll
            for (int rr = 0; rr < 4; rr++) g_EAtab[(size_t)rr * 512 + j] = act;
        }
        return;
    }
    int q = blockIdx.x;
    __shared__ float qe[KDIM];
    __shared__ float sh_d[MSLOT];
    __shared__ float sh_e[MSLOT];
    qe[t] = qe_table[q * KDIM + t];
    __syncthreads();
    float d = 0.0f;
    if (t < MSLOT) {
        #pragma unroll 8
        for (int k = 0; k < KDIM; k++) d = fmaf(qe[k], key_memory[t * KDIM + k], d);
        sh_d[t] = d;
    }
    __syncthreads();
    if (t < MSLOT) {
        float mx = -1e30f;
        #pragma unroll 8
        for (int i = 0; i < MSLOT; i++) mx = fmaxf(mx, sh_d[i]);
        sh_e[t] = expf(d - mx);
    }
    __syncthreads();
    if (t < MSLOT) {
        float sum = 0.0f;
        #pragma unroll 8
        for (int i = 0; i < MSLOT; i++) sum += sh_e[i];
        g_Wtab[q * MSLOT + t] = sh_e[t] / sum;
    }
    // perq projections
    {
        float acc = b_summary[t];
        #pragma unroll 8
        for (int dd = 0; dd < KDIM; dd++)
            acc = fmaf(qe[dd], W_summary[(256 + dd) * FDIM + t], acc);
        g_QStab[q * FDIM + t] = acc;
    }
    if (t < 3) {
        float a = b_beta[t];
        for (int dd = 0; dd < KDIM; dd++) a = fmaf(qe[dd], W_beta[dd * 3 + t], a);
        g_betatab[q * 3 + t] = a;
    } else if (t == 4) {
        float a = 0.0f;
        for (int dd = 0; dd < KDIM; dd++) a = fmaf(qe[dd], W_disc[128 + dd], a);
        g_qdtab[q] = a;
    }
}

// ---------------- K2: fused PP-GEMM + EA table -------------------------------
// C1[q,:] = Wv[q]·[We|Wa], C2[q,:] = Wv[5000+q]·[We|Wa]  (q = q_id-1, 0..4999)
// EA[q+1][r][col] = act( C1 + bvE2 + (r/3)·C2 )
__global__ void __launch_bounds__(256) ppea_kernel(const float* __restrict__ Wv,
                                                   const float* __restrict__ We,
                                                   const float* __restrict__ Wa) {
    const int K = 256;
    __shared__ float As1[8][128];  // duplicated pairs: 64 rows
    __shared__ float As2[8][128];
    __shared__ float Bs[8][128];
    int tid = threadIdx.x;
    int row0 = blockIdx.y * 64, col0 = blockIdx.x * 128;
    int lrow = (tid & 127) >> 1, ak4 = (tid & 1) * 4;
    int bK = tid >> 5, bCol = (tid & 31) * 4;
    int tx = tid & 15, ty = tid >> 4;
    ull acc1[4][4], acc2[4][4];
    #pragma unroll
    for (int i = 0; i < 4; i++)
        #pragma unroll
        for (int j = 0; j < 4; j++) { acc1[i][j] = 0ull; acc2[i][j] = 0ull; }

    int gr = row0 + lrow;
    bool valid = (gr < 5000);
    const float* aptr = Wv + ((tid < 128) ? (size_t)gr * K : (size_t)(5000 + gr) * K);
    for (int k0 = 0; k0 < K; k0 += 8) {
        float4 av = make_float4(0, 0, 0, 0);
        if (valid) av = __ldg((const float4*)(aptr + k0 + ak4));
        float (*As)[128] = (tid < 128) ? As1 : As2;
        *(float2*)&As[ak4 + 0][2 * lrow] = make_float2(av.x, av.x);
        *(float2*)&As[ak4 + 1][2 * lrow] = make_float2(av.y, av.y);
        *(float2*)&As[ak4 + 2][2 * lrow] = make_float2(av.z, av.z);
        *(float2*)&As[ak4 + 3][2 * lrow] = make_float2(av.w, av.w);
        int j = col0 + bCol;
        const float* bp = (j < 256) ? (We + (k0 + bK) * 256 + j)
                                    : (Wa + (k0 + bK) * 256 + (j - 256));
        *(float4*)&Bs[bK][bCol] = __ldg((const float4*)bp);
        __syncthreads();
        #pragma unroll
        for (int kk = 0; kk < 8; kk++) {
            ull ra1[4], ra2[4], rb[4];
            #pragma unroll
            for (int i = 0; i < 4; i++) {
                ra1[i] = *(const ull*)&As1[kk][2 * (ty * 4 + i)];
                ra2[i] = *(const ull*)&As2[kk][2 * (ty * 4 + i)];
            }
            #pragma unroll
            for (int jp = 0; jp < 4; jp++) rb[jp] = *(const ull*)&Bs[kk][jp * 32 + tx * 2];
            #pragma unroll
            for (int i = 0; i < 4; i++)
                #pragma unroll
                for (int jp = 0; jp < 4; jp++) {
                    acc1[i][jp] = fma2(ra1[i], rb[jp], acc1[i][jp]);
                    acc2[i][jp] = fma2(ra2[i], rb[jp], acc2[i][jp]);
                }
        }
        __syncthreads();
    }
    bool is_erase = (col0 < 256);
    #pragma unroll
    for (int i = 0; i < 4; i++) {
        int row = ty * 4 + i;
        int q = row0 + row;            // q_id - 1
        if (q >= 5000) continue;
        #pragma unroll
        for (int jp = 0; jp < 4; jp++) {
            int c = col0 + jp * 32 + tx * 2;
            float c1lo, c1hi, c2lo, c2hi;
            unpack2(acc1[i][jp], c1lo, c1hi);
            unpack2(acc2[i][jp], c2lo, c2hi);
            float blo = g_bvE2[c], bhi = g_bvE2[c + 1];
            float x1lo = c1lo + blo, x1hi = c1hi + bhi;
            #pragma unroll
            for (int rr = 0; rr < 4; rr++) {
                float sc = (float)rr * (1.0f / 3.0f);
                float xlo = fmaf(sc, c2lo, x1lo);
                float xhi = fmaf(sc, c2hi, x1hi);
                float olo = is_erase ? sigmoidf_(xlo) : tanhf(xlo);
                float ohi = is_erase ? sigmoidf_(xhi) : tanhf(xhi);
                *(float2*)&g_EAtab[((size_t)(q + 1) * 4 + rr) * 512 + c] = make_float2(olo, ohi);
            }
        }
    }
}

// ---------------- K3: persistent recurrence scan (smem w-ring, f32x2) --------
// 128 CTAs, 512 threads. Thread owns 2 v (2p, 2p+1) x 16 m (8 pairs).
// quarter = tid&3 (m range quarter*16..+16), p = tid>>2.
__device__ __forceinline__ void ea_pref(int q, int r, int p, float2& ee, float2& aa) {
    const float* ea = g_EAtab + (size_t)(q * 4 + r) * 512;
    ee = __ldg((const float2*)(ea + 2 * p));
    aa = __ldg((const float2*)(ea + 256 + 2 * p));
}

__device__ __forceinline__ void scan_step(ull* R0, ull* R1, const float* wrow,
                                          float2 ee, float2 aa,
                                          int quarter, float* outp) {
    ull W[8];
    {
        const ulonglong2* wp = (const ulonglong2*)wrow;
        ulonglong2 t0 = wp[0], t1 = wp[1], t2 = wp[2], t3 = wp[3];
        W[0] = t0.x; W[1] = t0.y; W[2] = t1.x; W[3] = t1.y;
        W[4] = t2.x; W[5] = t2.y; W[6] = t3.x; W[7] = t3.y;
    }
    ull ne0 = pack2(-ee.x, -ee.x), ne1 = pack2(-ee.y, -ee.y);
    ull a20 = pack2(aa.x, aa.x),   a21 = pack2(aa.y, aa.y);
    ull acc0a = 0ull, acc0b = 0ull, acc1a = 0ull, acc1b = 0ull;
    #pragma unroll
    for (int i = 0; i < 4; i++) {
        ull t0 = fma2(ne0, R0[i], a20);
        ull t1 = fma2(ne1, R1[i], a21);
        acc0a = fma2(W[i], R0[i], acc0a);
        acc1a = fma2(W[i], R1[i], acc1a);
        R0[i] = fma2(W[i], t0, R0[i]);
        R1[i] = fma2(W[i], t1, R1[i]);
    }
    #pragma unroll
    for (int i = 4; i < 8; i++) {
        ull t0 = fma2(ne0, R0[i], a20);
        ull t1 = fma2(ne1, R1[i], a21);
        acc0b = fma2(W[i], R0[i], acc0b);
        acc1b = fma2(W[i], R1[i], acc1b);
        R0[i] = fma2(W[i], t0, R0[i]);
        R1[i] = fma2(W[i], t1, R1[i]);
    }
    float x0a, y0a, x0b, y0b, x1a, y1a, x1b, y1b;
    unpack2(acc0a, x0a, y0a); unpack2(acc0b, x0b, y0b);
    unpack2(acc1a, x1a, y1a); unpack2(acc1b, x1b, y1b);
    float rd0 = (x0a + x0b) + (y0a + y0b);
    float rd1 = (x1a + x1b) + (y1a + y1b);
    rd0 += __shfl_xor_sync(0xffffffffu, rd0, 1);
    rd0 += __shfl_xor_sync(0xffffffffu, rd0, 2);
    rd1 += __shfl_xor_sync(0xffffffffu, rd1, 1);
    rd1 += __shfl_xor_sync(0xffffffffu, rd1, 2);
    if (quarter == 0) *(float2*)outp = make_float2(rd0, rd1);
}

__global__ void __launch_bounds__(512) scan_kernel(const int* __restrict__ q_data,
                                                   const int* __restrict__ r_data,
                                                   const float* __restrict__ initMv) {
    const int b = blockIdx.x;
    const int tid = threadIdx.x;
    const int quarter = tid & 3;
    const int p = tid >> 2;

    __shared__ int q_sh[SS + 8];
    __shared__ int r_sh[SS + 8];
    __shared__ float wring[64 * MSLOT];   // 64 steps x 64 floats = 16KB

    for (int i = tid; i < SS; i += 512) {
        q_sh[i] = q_data[b * SS + i];
        r_sh[i] = r_data[b * SS + i];
    }
    if (tid < 8) {
        q_sh[SS + tid] = q_data[b * SS + SS - 1];
        r_sh[SS + tid] = r_data[b * SS + SS - 1];
    }

    ull R0[8], R1[8];
    #pragma unroll
    for (int i = 0; i < 8; i++) {
        int m = quarter * 16 + 2 * i;
        R0[i] = pack2(initMv[m * VDIM + 2 * p],     initMv[(m + 1) * VDIM + 2 * p]);
        R1[i] = pack2(initMv[m * VDIM + 2 * p + 1], initMv[(m + 1) * VDIM + 2 * p + 1]);
    }
    __syncthreads();

    float2 eA, aA, eB, aB, eC, aC, eD, aD;
    ea_pref(q_sh[0], r_sh[0], p, eA, aA);
    ea_pref(q_sh[1], r_sh[1], p, eB, aB);
    ea_pref(q_sh[2], r_sh[2], p, eC, aC);

    float* rdbase = g_read + (((size_t)b << 10)) * VDIM + 2 * p;
    const int qoff = quarter * 16;

    #pragma unroll 1
    for (int c = 0; c < 16; c++) {
        __syncthreads();   // prior chunk fully consumed before ring overwrite
        {   // cooperative refill: 64 steps x 64 floats, 2 float4 per thread
            int u = tid * 2;
            int sl = u >> 4;
            int fi = u & 15;
            const float* src = g_Wtab + q_sh[c * 64 + sl] * MSLOT;
            *(float4*)&wring[sl * MSLOT + fi * 4]       = __ldg((const float4*)(src + fi * 4));
            *(float4*)&wring[sl * MSLOT + (fi + 1) * 4] = __ldg((const float4*)(src + (fi + 1) * 4));
        }
        __syncthreads();
        int base = c * 64;
        #pragma unroll 1
        for (int k = 0; k < 16; k++) {
            int s = base + k * 4;
            ea_pref(q_sh[s + 3], r_sh[s + 3], p, eD, aD);
            scan_step(R0, R1, &wring[((s) & 63) * MSLOT + qoff], eA, aA, quarter,
                      rdbase + (size_t)s * VDIM);
            ea_pref(q_sh[s + 4], r_sh[s + 4], p, eA, aA);
            scan_step(R0, R1, &wring[((s + 1) & 63) * MSLOT + qoff], eB, aB, quarter,
                      rdbase + (size_t)(s + 1) * VDIM);
            ea_pref(q_sh[s + 5], r_sh[s + 5], p, eB, aB);
            scan_step(R0, R1, &wring[((s + 2) & 63) * MSLOT + qoff], eC, aC, quarter,
                      rdbase + (size_t)(s + 2) * VDIM);
            ea_pref(q_sh[s + 6], r_sh[s + 6], p, eC, aC);
            scan_step(R0, R1, &wring[((s + 3) & 63) * MSLOT + qoff], eD, aD, quarter,
                      rdbase + (size_t)(s + 3) * VDIM);
        }
    }
}

// ---------------- K4: summary SGEMM (131072x256 @ 256x128), f32x2, tanh ------
__global__ void __launch_bounds__(256) sgemm_sum_kernel(const int* __restrict__ q_data,
                                                        const float* __restrict__ W_summary) {
    const int K = 256, N = 128;
    __shared__ float As[8][256];   // duplicated
    __shared__ float Bs[8][128];
    __shared__ int qrow_s[128];
    int tid = threadIdx.x;
    int row0 = blockIdx.x * 128;
    if (tid < 128) qrow_s[tid] = q_data[row0 + tid];
    int aRow = tid >> 1, aK4 = (tid & 1) * 4;
    int bK = tid >> 5, bCol = (tid & 31) * 4;
    int tx = tid & 15, ty = tid >> 4;
    ull acc2[8][4];
    #pragma unroll
    for (int i = 0; i < 8; i++)
        #pragma unroll
        for (int j = 0; j < 4; j++) acc2[i][j] = 0ull;

    const float* A = g_read;
    for (int k0 = 0; k0 < K; k0 += 8) {
        float4 av = __ldg((const float4*)(A + (size_t)(row0 + aRow) * K + k0 + aK4));
        *(float2*)&As[aK4 + 0][2 * aRow] = make_float2(av.x, av.x);
        *(float2*)&As[aK4 + 1][2 * aRow] = make_float2(av.y, av.y);
        *(float2*)&As[aK4 + 2][2 * aRow] = make_float2(av.z, av.z);
        *(float2*)&As[aK4 + 3][2 * aRow] = make_float2(av.w, av.w);
        *(float4*)&Bs[bK][bCol] = __ldg((const float4*)(W_summary + (k0 + bK) * N + bCol));
        __syncthreads();
        #pragma unroll
        for (int kk = 0; kk < 8; kk++) {
            ull ra[8], rb[4];
            #pragma unroll
            for (int i = 0; i < 8; i++) ra[i] = *(const ull*)&As[kk][2 * (ty * 8 + i)];
            #pragma unroll
            for (int jp = 0; jp < 4; jp++) rb[jp] = *(const ull*)&Bs[kk][jp * 32 + tx * 2];
            #pragma unroll
            for (int i = 0; i < 8; i++)
                #pragma unroll
                for (int jp = 0; jp < 4; jp++)
                    acc2[i][jp] = fma2(ra[i], rb[jp], acc2[i][jp]);
        }
        __syncthreads();
    }
    #pragma unroll
    for (int i = 0; i < 8; i++) {
        int rl = ty * 8 + i;
        int r = row0 + rl;
        int q = qrow_s[rl];
        const float* qs = g_QStab + q * FDIM;
        #pragma unroll
        for (int jp = 0; jp < 4; jp++) {
            int c = jp * 32 + tx * 2;
            float lo, hi; unpack2(acc2[i][jp], lo, hi);
            *(float2*)&g_summary[(size_t)r * N + c] =
                make_float2(tanhf(lo + __ldg(qs + c)), tanhf(hi + __ldg(qs + c + 1)));
        }
    }
}

// ---------------- K5: per-token head (theta/alpha/CORAL), 32 tokens/warp -----
__global__ void __launch_bounds__(256) head_kernel(const int* __restrict__ q_data,
                                                   const float* __restrict__ W_theta,
                                                   const float* __restrict__ b_theta,
                                                   const float* __restrict__ W_disc,
                                                   const float* __restrict__ b_disc,
                                                   const float* __restrict__ W_c1,
                                                   const float* __restrict__ b_c1,
                                                   const float* __restrict__ W_c2,
                                                   const float* __restrict__ b_c2,
                                                   const float* __restrict__ coral_w,
                                                   const float* __restrict__ coral_b,
                                                   float* __restrict__ out) {
    __shared__ float sWc1[5 * 64], sBc1[64], sWc2[64 * 32], sBc2[32], sCw[32];
    __shared__ float sWth[128], sWd[128];
    __shared__ float h1s[8][64];
    int tid = threadIdx.x;
    for (int i = tid; i < 320; i += 256) sWc1[i] = W_c1[i];
    for (int i = tid; i < 2048; i += 256) sWc2[i] = W_c2[i];
    if (tid < 64) sBc1[tid] = b_c1[tid];
    if (tid < 32) { sBc2[tid] = b_c2[tid]; sCw[tid] = coral_w[tid]; }
    if (tid < 128) { sWth[tid] = W_theta[tid]; sWd[tid] = W_disc[tid]; }
    __syncthreads();

    int warp = tid >> 5, lane = tid & 31;
    float bth = b_theta[0], bd = b_disc[0];
    float cb0 = coral_b[0], cb1 = coral_b[1], cb2 = coral_b[2];
    float wth0 = sWth[lane], wth1 = sWth[lane + 32], wth2 = sWth[lane + 64], wth3 = sWth[lane + 96];
    float wd0 = sWd[lane], wd1 = sWd[lane + 32], wd2 = sWd[lane + 64], wd3 = sWd[lane + 96];
    float cw = sCw[lane];

    const int TOK = 32;
    size_t base = ((size_t)blockIdx.x * 8 + warp) * TOK;
    for (int t = 0; t < TOK; t++) {
        size_t n = base + t;
        const float* srow = g_summary + n * FDIM;
        float s0 = __ldg(srow + lane), s1 = __ldg(srow + lane + 32);
        float s2 = __ldg(srow + lane + 64), s3 = __ldg(srow + lane + 96);
        float th = s0 * wth0 + s1 * wth1 + s2 * wth2 + s3 * wth3;
        float dp = s0 * wd0 + s1 * wd1 + s2 * wd2 + s3 * wd3;
        #pragma unroll
        for (int o = 16; o; o >>= 1) {
            th += __shfl_xor_sync(0xffffffffu, th, o);
            dp += __shfl_xor_sync(0xffffffffu, dp, o);
        }
        float theta = (th + bth) * 3.0f;
        int q = q_data[n];
        float alpha = softplusf_(dp + g_qdtab[q] + bd);
        float be0 = g_betatab[q * 3 + 0];
        float be1 = g_betatab[q * 3 + 1];
        float be2 = g_betatab[q * 3 + 2];
        float feat[5] = {theta, alpha, be0, be1, be2};

        float h1a = sBc1[lane], h1b = sBc1[lane + 32];
        #pragma unroll
        for (int i = 0; i < 5; i++) {
            h1a = fmaf(feat[i], sWc1[i * 64 + lane], h1a);
            h1b = fmaf(feat[i], sWc1[i * 64 + lane + 32], h1b);
        }
        h1s[warp][lane] = fmaxf(h1a, 0.0f);
        h1s[warp][lane + 32] = fmaxf(h1b, 0.0f);
        __syncwarp();
        float h2 = sBc2[lane];
        #pragma unroll
        for (int i = 0; i < 64; i++) h2 = fmaf(h1s[warp][i], sWc2[i * 32 + lane], h2);
        h2 = fmaxf(h2, 0.0f);
        float lg = h2 * cw;
        #pragma unroll
        for (int o = 16; o; o >>= 1) lg += __shfl_xor_sync(0xffffffffu, lg, o);

        if (lane == 0) {
            float l0 = lg + cb0, l1 = lg + cb1, l2 = lg + cb2;
            float c1 = sigmoidf_(l0);
            float c2 = c1 * sigmoidf_(l1);
            float c3 = c2 * sigmoidf_(l2);
            const size_t N = NT;
            out[n] = theta;
            out[N + n * 3 + 0] = be0;
            out[N + n * 3 + 1] = be1;
            out[N + n * 3 + 2] = be2;
            out[4 * N + n] = alpha;
            out[5 * N + n * 4 + 0] = 1.0f - c1;
            out[5 * N + n * 4 + 1] = c1 - c2;
            out[5 * N + n * 4 + 2] = c2 - c3;
            out[5 * N + n * 4 + 3] = c3;
            out[9 * N + n * 3 + 0] = l0;
            out[9 * N + n * 3 + 1] = l1;
            out[9 * N + n * 3 + 2] = l2;
        }
        __syncwarp();
    }
}

// ---------------- launch -----------------------------------------------------
extern "C" void kernel_launch(void* const* d_in, const int* in_sizes, int n_in,
                              void* d_out, int out_size) {
    const int*   q_data   = (const int*)d_in[0];
    const int*   r_data   = (const int*)d_in[1];
    const float* qe_table = (const float*)d_in[2];
    const float* key_mem  = (const float*)d_in[3];
    const float* initMv   = (const float*)d_in[4];
    const float* W_value  = (const float*)d_in[5];
    const float* b_value  = (const float*)d_in[6];
    const float* W_erase  = (const float*)d_in[7];
    const float* b_erase  = (const float*)d_in[8];
    const float* W_add    = (const float*)d_in[9];
    const float* b_add    = (const float*)d_in[10];
    const float* W_summary= (const float*)d_in[11];
    const float* b_summary= (const float*)d_in[12];
    const float* W_theta  = (const float*)d_in[13];
    const float* b_theta  = (const float*)d_in[14];
    const float* W_beta   = (const float*)d_in[15];
    const float* b_beta   = (const float*)d_in[16];
    const float* W_disc   = (const float*)d_in[17];
    const float* b_disc   = (const float*)d_in[18];
    const float* W_c1     = (const float*)d_in[19];
    const float* b_c1     = (const float*)d_in[20];
    const float* W_c2     = (const float*)d_in[21];
    const float* b_c2     = (const float*)d_in[22];
    const float* coral_w  = (const float*)d_in[23];
    const float* coral_b  = (const float*)d_in[24];
    float* out = (float*)d_out;

    // L1: wtab + perq + bv
    wtab_perq_kernel<<<QMAX + 1, 128>>>(qe_table, key_mem, b_value, W_erase, W_add,
                                        b_erase, b_add, W_summary, b_summary,
                                        W_beta, b_beta, W_disc);
    // L2: fused PP GEMM + EA table
    {
        dim3 g(4, 79);   // 4 col-tiles x 79 row-tiles (64 rows each, covers 5000)
        ppea_kernel<<<g, 256>>>(W_value, W_erase, W_add);
    }
    // L3: scan
    scan_kernel<<<BB, 512>>>(q_data, r_data, initMv);
    // L4: summary GEMM (<- ncu capture slot)
    sgemm_sum_kernel<<<NT / 128, 256>>>(q_data, W_summary);
    // L5: head
    head_kernel<<<NT / (8 * 32), 256>>>(q_data, W_theta, b_theta, W_disc, b_disc,
                                        W_c1, b_c1, W_c2, b_c2, coral_w, coral_b, out);
}